// round 15
// baseline (speedup 1.0000x reference)
#include <cuda_runtime.h>
#include <cstdint>

#define BB 16
#define NN 25200
#define NCC 80
#define SCAP 384            // per (image,class) candidate cap (mean ~227, sigma ~15 -> >10 sigma)
#define PMAX 512            // sort pad (next pow2 >= SCAP)
#define MAXDET 300
#define CONF_T 0.25f
#define IOU_T 0.45f
#define CLS_OFF 4096.0f
#define GCAP 4096
#define PB 128              // boxes per k_prep block

typedef unsigned long long u64;

// ---------------- scratch (static device globals; no allocation) ----------------
__device__ float g_score[BB * NN];        // conf if valid else -1
__device__ float g_clsf[BB * NN];         // best class as float
__device__ float g_box[BB * NN * 4];      // xyxy (raw, un-offset)
__device__ float g_surv[BB * NN];         // survivor conf else -1
__device__ int   g_cnt[BB * NCC];         // per (image,class) candidate count
__device__ int   g_cand[BB * NCC * SCAP]; // per (image,class) candidate box indices (global m)

// ---------------- kernel 0: zero counters ----------------
__global__ void k_init() {
    int i = blockIdx.x * blockDim.x + threadIdx.x;
    if (i < BB * NCC) g_cnt[i] = 0;
}

// ---------------- kernel 1: per-box prep (one thread per box, smem staging) ----------------
__global__ void __launch_bounds__(PB) k_prep(const float* __restrict__ pred) {
    __shared__ float s[PB * 85];          // 43520 B
    int m0 = blockIdx.x * PB;
    int t = threadIdx.x;
    const float* base = pred + (size_t)m0 * 85;

    // coalesced stage: 85 iterations of 128 consecutive floats
    #pragma unroll
    for (int r = 0; r < 85; r++) {
        int idx = r * PB + t;
        s[idx] = base[idx];
    }
    __syncthreads();

    int m = m0 + t;
    const float* row = &s[t * 85];        // stride 85 floats: gcd(85,32)=1 -> conflict-free
    float obj = row[4];

    // exact: p = cls * obj elementwise, then first-index argmax (strict > keeps lowest c)
    float bv = -1e30f; int bc = 0;
    #pragma unroll 8
    for (int c = 0; c < NCC; c++) {
        float p = __fmul_rn(row[5 + c], obj);
        if (p > bv) { bv = p; bc = c; }
    }

    float cx = row[0], cy = row[1], w = row[2], h = row[3];
    float hw = __fmul_rn(w, 0.5f), hh = __fmul_rn(h, 0.5f);
    float x1 = __fsub_rn(cx, hw), y1 = __fsub_rn(cy, hh);
    float x2 = __fadd_rn(cx, hw), y2 = __fadd_rn(cy, hh);
    *(float4*)&g_box[(size_t)m * 4] = make_float4(x1, y1, x2, y2);

    bool valid = (obj > CONF_T) && (bv > CONF_T);
    g_score[m] = valid ? bv : -1.0f;
    g_clsf[m]  = (float)bc;
    g_surv[m]  = -1.0f;
    if (valid) {
        int b = m / NN;
        int slot = b * NCC + bc;
        int pos = atomicAdd(&g_cnt[slot], 1);
        if (pos < SCAP) g_cand[slot * SCAP + pos] = m;
    }
}

// ---------------- kernel 2: per (image,class) NMS: sort + lazy survivor-list greedy ----------------
// Exactly equivalent to sequential greedy NMS: in (score desc, id asc) order, a candidate
// survives iff no already-accepted survivor has IoU > thr with it. Survivors tested
// warp-parallel; appended in rank order.
__global__ void __launch_bounds__(128) k_nms() {
    __shared__ u64    s_key[PMAX];          // (~score_bits)<<32 | m  (ascending == score desc, id asc)
    __shared__ float4 s_bx[SCAP];           // offset candidate boxes (sorted order)
    __shared__ float  s_ar[SCAP];           // candidate areas
    __shared__ float4 s_sbx[SCAP];          // survivor boxes
    __shared__ float  s_sar[SCAP];          // survivor areas

    int slot = blockIdx.x;
    int k = g_cnt[slot];
    if (k > SCAP) k = SCAP;
    if (k == 0) return;
    int c = slot % NCC;
    float joff = __fmul_rn((float)c, CLS_OFF);
    int tid = threadIdx.x;
    const int* cand = &g_cand[slot * SCAP];

    // dynamic sort size: next pow2 >= k
    int P = 64; while (P < k) P <<= 1;

    // load keys (pad with max)
    for (int i = tid; i < P; i += 128) {
        u64 key = ~0ull;
        if (i < k) {
            int m = cand[i];
            unsigned u = __float_as_uint(g_score[m]);   // scores > 0.25 -> positive floats, order == bit order
            key = ((u64)(~u) << 32) | (unsigned)m;
        }
        s_key[i] = key;
    }
    __syncthreads();

    // bitonic sort ascending
    for (int kk = 2; kk <= P; kk <<= 1) {
        for (int j = kk >> 1; j > 0; j >>= 1) {
            for (int i = tid; i < P; i += 128) {
                int ixj = i ^ j;
                if (ixj > i) {
                    u64 a = s_key[i], b = s_key[ixj];
                    bool up = ((i & kk) == 0);
                    if ((a > b) == up) { s_key[i] = b; s_key[ixj] = a; }
                }
            }
            __syncthreads();
        }
    }

    // decode: offset boxes + areas in sorted order
    for (int i = tid; i < k; i += 128) {
        int m = (int)(unsigned)s_key[i];
        float4 bx = *(const float4*)&g_box[(size_t)m * 4];
        float x1 = __fadd_rn(bx.x, joff);
        float y1 = __fadd_rn(bx.y, joff);
        float x2 = __fadd_rn(bx.z, joff);
        float y2 = __fadd_rn(bx.w, joff);
        s_bx[i] = make_float4(x1, y1, x2, y2);
        s_ar[i] = __fmul_rn(__fsub_rn(x2, x1), __fsub_rn(y2, y1));
    }
    __syncthreads();

    // lazy greedy scan: warp 0 walks candidates in rank order, testing each against
    // the survivor list in parallel across lanes.
    if (tid < 32) {
        int lane = tid;
        int ns = 0;
        for (int i = 0; i < k; i++) {
            float4 bi = s_bx[i];                   // broadcast LDS
            float  ai = s_ar[i];
            int supp = 0;
            for (int s = lane; s < ns; s += 32) {
                float4 bs = s_sbx[s];
                float iw = __fsub_rn(fminf(bs.z, bi.z), fmaxf(bs.x, bi.x));
                float ih = __fsub_rn(fminf(bs.w, bi.w), fmaxf(bs.y, bi.y));
                if (iw > 0.0f && ih > 0.0f) {      // inter==0 -> iou==0 -> no suppression (exact)
                    float inter = __fmul_rn(iw, ih);
                    float denom = __fadd_rn(__fsub_rn(__fadd_rn(s_sar[s], ai), inter), 1e-9f);
                    if (__fdiv_rn(inter, denom) > IOU_T) supp = 1;
                }
            }
            if (!__any_sync(0xffffffffu, supp)) {
                if (lane == 0) {
                    s_sbx[ns] = bi;
                    s_sar[ns] = ai;
                    u64 key = s_key[i];
                    g_surv[(int)(unsigned)key] = __uint_as_float(~(unsigned)(key >> 32));
                }
                ns++;
            }
            __syncwarp();                          // survivor STS visible before next iteration
        }
    }
}

// ---------------- kernel 3: per-image top-300 via 2048-bin radix select + bitonic sort ----------------
// Scores are in (0.25, 0.9] => float bits [31:25] are constant 0x1F, so bits [24:14]
// (11 bits) are a monotone order prefix with good bin spread.
__global__ void __launch_bounds__(1024) k_select(const float* __restrict__ logits,
                                                 float* __restrict__ out) {
    __shared__ int hist[2048];
    __shared__ int psum[256];
    __shared__ u64 gkey[GCAP];
    __shared__ int s_cnt, s_total, s_pv;

    int b = blockIdx.x, t = threadIdx.x;
    const float* surv = &g_surv[(size_t)b * NN];

    for (int i = t; i < 2048; i += 1024) hist[i] = 0;
    __syncthreads();

    // single histogram sweep
    for (int i = t; i < NN; i += 1024) {
        float v = surv[i];
        if (v > 0.0f) atomicAdd(&hist[(__float_as_uint(v) >> 14) & 2047], 1);
    }
    __syncthreads();

    // pivot: parallel partial sums (8 bins per thread), then short serial scans
    if (t < 256) {
        int s = 0;
        #pragma unroll
        for (int x = 0; x < 8; x++) s += hist[t * 8 + x];
        psum[t] = s;
    }
    __syncthreads();
    if (t == 0) {
        int total = 0;
        for (int g = 0; g < 256; g++) total += psum[g];
        s_total = total;
        int pv = 0;
        if (total >= MAXDET) {
            int cum = 0, g = 255;
            for (; g > 0; g--) {
                if (cum + psum[g] >= MAXDET) break;
                cum += psum[g];
            }
            int x = 7;
            for (; x > 0; x--) {
                int h = hist[g * 8 + x];
                if (cum + h >= MAXDET) break;
                cum += h;
            }
            pv = g * 8 + x;
        }
        s_pv = pv;      // take all bins >= pv  (pv=0 when total<300: take everything)
    }
    __syncthreads();
    int PV = s_pv;

    // gather: everything in bins >= pivot bin
    if (t == 0) s_cnt = 0;
    __syncthreads();
    for (int i = t; i < NN; i += 1024) {
        float v = surv[i];
        if (v > 0.0f) {
            unsigned u = __float_as_uint(v);
            if ((int)((u >> 14) & 2047) >= PV) {
                int s = atomicAdd(&s_cnt, 1);
                if (s < GCAP) gkey[s] = ((u64)(~u) << 32) | (unsigned)i;
            }
        }
    }
    __syncthreads();
    int M = s_cnt; if (M > GCAP) M = GCAP;

    // pad to power of 2 and bitonic sort ascending
    int P = 512; while (P < M) P <<= 1;
    for (int i = M + t; i < P; i += 1024) gkey[i] = ~0ull;
    __syncthreads();
    for (int kk = 2; kk <= P; kk <<= 1) {
        for (int j = kk >> 1; j > 0; j >>= 1) {
            for (int i = t; i < P; i += 1024) {
                int ixj = i ^ j;
                if (ixj > i) {
                    u64 a = gkey[i], bb = gkey[ixj];
                    bool up = ((i & kk) == 0);
                    if ((a > bb) == up) { gkey[i] = bb; gkey[ixj] = a; }
                }
            }
            __syncthreads();
        }
    }

    int kept_n = s_total < MAXDET ? s_total : MAXDET;

    // --- outputs, fully parallel ---
    // dets [BB,300,6]
    for (int e = t; e < MAXDET * 6; e += 1024) {
        int d = e / 6, f = e - d * 6;
        float val = 0.0f;
        if (d < kept_n) {
            u64 key = gkey[d];
            int m = (int)(unsigned)key;
            if (f < 4)      val = g_box[((size_t)b * NN + m) * 4 + f];
            else if (f == 4) val = __uint_as_float(~(unsigned)(key >> 32));
            else             val = g_clsf[(size_t)b * NN + m];
        }
        out[(size_t)b * MAXDET * 6 + e] = val;
    }
    // lg [BB,300,80]
    const size_t LG0 = (size_t)BB * MAXDET * 6;
    for (int e = t; e < MAXDET * 80; e += 1024) {
        int d = e / 80, cc = e - d * 80;
        float val = 0.0f;
        if (d < kept_n) {
            int m = (int)(unsigned)gkey[d];
            val = logits[((size_t)b * NN + m) * 80 + cc];
        }
        out[LG0 + (size_t)b * MAXDET * 80 + e] = val;
    }
    // keep [BB,300]
    const size_t KP0 = (size_t)BB * MAXDET * 86;
    for (int e = t; e < MAXDET; e += 1024) {
        out[KP0 + (size_t)b * MAXDET + e] = (e < kept_n) ? 1.0f : 0.0f;
    }
}

// ---------------- launch ----------------
extern "C" void kernel_launch(void* const* d_in, const int* in_sizes, int n_in,
                              void* d_out, int out_size) {
    const float* pred   = (const float*)d_in[0];
    const float* logits = (const float*)d_in[1];
    float* out = (float*)d_out;

    k_init<<<(BB * NCC + 255) / 256, 256>>>();
    k_prep<<<BB * NN / PB, PB>>>(pred);     // 3150 blocks, one thread per box
    k_nms<<<BB * NCC, 128>>>();
    k_select<<<BB, 1024>>>(logits, out);
}

// round 16
// speedup vs baseline: 1.4095x; 1.4095x over previous
#include <cuda_runtime.h>
#include <cstdint>

#define BB 16
#define NN 25200
#define NCC 80
#define SCAP 384            // per (image,class) candidate cap (mean ~227, sigma ~15 -> >10 sigma)
#define WMAX 6              // SCAP/64 mask words
#define MAXDET 300
#define CONF_T 0.25f
#define IOU_T 0.45f
#define CLS_OFF 4096.0f
#define GCAP 4096
#define PB 128              // boxes per k_prep block

typedef unsigned long long u64;

// ---------------- scratch (static device globals; no allocation) ----------------
__device__ float g_score[BB * NN];        // conf if valid else -1
__device__ float g_clsf[BB * NN];         // best class as float
__device__ float g_box[BB * NN * 4];      // xyxy (raw, un-offset)
__device__ float g_surv[BB * NN];         // survivor conf else -1
__device__ int   g_cnt[BB * NCC];         // per (image,class) candidate count (zero-init; reset by k_nms)
__device__ int   g_cand[BB * NCC * SCAP]; // per (image,class) candidate box indices (global m)

// ---------------- kernel 1: per-box prep (one thread per box, smem staging) ----------------
__global__ void __launch_bounds__(PB) k_prep(const float* __restrict__ pred) {
    __shared__ float s[PB * 85];          // 43520 B
    int m0 = blockIdx.x * PB;
    int t = threadIdx.x;
    const float* base = pred + (size_t)m0 * 85;

    // coalesced stage: 85 iterations of 128 consecutive floats
    #pragma unroll
    for (int r = 0; r < 85; r++) {
        int idx = r * PB + t;
        s[idx] = base[idx];
    }
    __syncthreads();

    int m = m0 + t;
    const float* row = &s[t * 85];        // stride 85 floats: gcd(85,32)=1 -> conflict-free
    float obj = row[4];

    // exact: p = cls * obj elementwise, then first-index argmax (strict > keeps lowest c)
    float bv = -1e30f; int bc = 0;
    #pragma unroll 8
    for (int c = 0; c < NCC; c++) {
        float p = __fmul_rn(row[5 + c], obj);
        if (p > bv) { bv = p; bc = c; }
    }

    float cx = row[0], cy = row[1], w = row[2], h = row[3];
    float hw = __fmul_rn(w, 0.5f), hh = __fmul_rn(h, 0.5f);
    float x1 = __fsub_rn(cx, hw), y1 = __fsub_rn(cy, hh);
    float x2 = __fadd_rn(cx, hw), y2 = __fadd_rn(cy, hh);
    *(float4*)&g_box[(size_t)m * 4] = make_float4(x1, y1, x2, y2);

    bool valid = (obj > CONF_T) && (bv > CONF_T);
    g_score[m] = valid ? bv : -1.0f;
    g_clsf[m]  = (float)bc;
    g_surv[m]  = -1.0f;
    if (valid) {
        int b = m / NN;
        int slot = b * NCC + bc;
        int pos = atomicAdd(&g_cnt[slot], 1);
        if (pos < SCAP) g_cand[slot * SCAP + pos] = m;
    }
}

// ---------------- kernel 2: per (image,class) NMS via sort + bitmask + group-serial warp scan ----
// Exactly equivalent to sequential greedy NMS:
//   sort by (score desc, id asc); box i survives iff no earlier *survivor* has IoU > thr.
__global__ void __launch_bounds__(256) k_nms() {
    __shared__ u64    s_key[SCAP];          // (~score_bits)<<32 | m  (ascending == score desc, id asc)
    __shared__ float4 s_bx[SCAP];           // offset box x1,y1,x2,y2
    __shared__ float  s_ar[SCAP];           // area
    __shared__ u64    s_mask[SCAP * WMAX];  // row i: bits j>i with IoU>thr (stride W)

    int slot = blockIdx.x;
    int k = g_cnt[slot];
    if (k > SCAP) k = SCAP;
    if (k == 0) return;                     // g_cnt already 0: no reset needed
    int c = slot % NCC;
    float joff = __fmul_rn((float)c, CLS_OFF);
    int tid = threadIdx.x;
    const int* cand = &g_cand[slot * SCAP];

    // dynamic sort size: next pow2 >= k
    int P = 64; while (P < k) P <<= 1;

    // load keys (pad with max)
    for (int i = tid; i < P; i += 256) {
        u64 key = ~0ull;
        if (i < k) {
            int m = cand[i];
            unsigned u = __float_as_uint(g_score[m]);   // scores > 0.25 -> positive floats, order == bit order
            key = ((u64)(~u) << 32) | (unsigned)m;
        }
        s_key[i] = key;
    }
    __syncthreads();
    if (tid == 0) g_cnt[slot] = 0;          // reset for next run (replaces k_init)

    // bitonic sort ascending
    for (int kk = 2; kk <= P; kk <<= 1) {
        for (int j = kk >> 1; j > 0; j >>= 1) {
            for (int i = tid; i < P; i += 256) {
                int ixj = i ^ j;
                if (ixj > i) {
                    u64 a = s_key[i], b = s_key[ixj];
                    bool up = ((i & kk) == 0);
                    if ((a > b) == up) { s_key[i] = b; s_key[ixj] = a; }
                }
            }
            __syncthreads();
        }
    }

    // decode: load offset boxes in sorted order + precompute areas
    for (int i = tid; i < k; i += 256) {
        int m = (int)(unsigned)s_key[i];
        float4 bx = *(const float4*)&g_box[(size_t)m * 4];
        float x1 = __fadd_rn(bx.x, joff);
        float y1 = __fadd_rn(bx.y, joff);
        float x2 = __fadd_rn(bx.z, joff);
        float y2 = __fadd_rn(bx.w, joff);
        s_bx[i] = make_float4(x1, y1, x2, y2);
        s_ar[i] = __fmul_rn(__fsub_rn(x2, x1), __fsub_rn(y2, y1));
    }
    __syncthreads();

    // suppression bit-matrix (parallel over (row, word))
    // Early-exit: inter==0 -> iou==0 -> never > 0.45 (denom > 0), exactly as reference.
    int W = (k + 63) >> 6;
    int totw = k * W;
    for (int x = tid; x < totw; x += 256) {
        int i = x / W, w = x - i * W;
        float4 bi = s_bx[i];
        float a1 = s_ar[i];
        u64 mword = 0;
        int j0 = w << 6;
        int jlo = (j0 > i + 1) ? j0 : (i + 1);
        int jhi = (j0 + 64 < k) ? (j0 + 64) : k;
        for (int j = jlo; j < jhi; j++) {
            float4 bj = s_bx[j];                        // single LDS.128
            float iw = __fsub_rn(fminf(bi.z, bj.z), fmaxf(bi.x, bj.x));
            float ih = __fsub_rn(fminf(bi.w, bj.w), fmaxf(bi.y, bj.y));
            if (iw > 0.0f && ih > 0.0f) {               // ~3% of pairs
                float inter = __fmul_rn(iw, ih);
                float denom = __fadd_rn(__fsub_rn(__fadd_rn(a1, s_ar[j]), inter), 1e-9f);
                if (__fdiv_rn(inter, denom) > IOU_T) mword |= 1ull << (j - j0);
            }
        }
        s_mask[i * W + w] = mword;
    }
    __syncthreads();

    // group-serial warp scan: lane g owns rem word g. For each 64-candidate group g:
    //   lane g decides its group's candidates serially in registers (no shfl per candidate),
    //   then one 64-bit shfl broadcasts the group's survivor mask; later lanes OR the
    //   survivors' mask words in parallel. Semantics identical to the sequential scan.
    if (tid < 32) {
        int lane = tid;
        u64 rem = 0;
        u64 surv_all[WMAX];
        #pragma unroll
        for (int g = 0; g < WMAX; g++) surv_all[g] = 0;

        for (int g = 0; g < W; g++) {
            u64 survm = 0;
            if (lane == g) {
                int i0 = g << 6;
                int n = k - i0; if (n > 64) n = 64;
                for (int b = 0; b < n; b++) {
                    if (!((rem >> b) & 1ull)) {
                        survm |= 1ull << b;
                        rem |= s_mask[(i0 + b) * W + g];   // suppress later same-group candidates
                    }
                }
            }
            survm = __shfl_sync(0xffffffffu, survm, g);
            #pragma unroll
            for (int gg = 0; gg < WMAX; gg++) if (gg == g) surv_all[gg] = survm;
            if (lane > g && lane < W) {
                u64 sm = survm;
                int i0 = g << 6;
                while (sm) {
                    int b = __ffsll((long long)sm) - 1;
                    sm &= sm - 1;
                    rem |= s_mask[(i0 + b) * W + lane];    // independent LDS, pipelined
                }
            }
        }

        // parallel survivor writeback: lane L handles bits L and L+32 of each group word
        #pragma unroll
        for (int g = 0; g < WMAX; g++) {
            if (g < W) {
                u64 sm = surv_all[g];
                #pragma unroll
                for (int h = 0; h < 2; h++) {
                    int b = lane + h * 32;
                    if ((sm >> b) & 1ull) {
                        u64 key = s_key[(g << 6) + b];
                        g_surv[(int)(unsigned)key] = __uint_as_float(~(unsigned)(key >> 32));
                    }
                }
            }
        }
    }
}

// ---------------- kernel 3: per-image top-300 via 2048-bin radix select + bitonic sort ----------------
// Scores are in (0.25, 0.9] => float bits [31:25] are constant 0x1F, so bits [24:14]
// (11 bits) are a monotone order prefix with good bin spread.
__global__ void __launch_bounds__(1024) k_select(const float* __restrict__ logits,
                                                 float* __restrict__ out) {
    __shared__ int hist[2048];
    __shared__ int psum[256];
    __shared__ u64 gkey[GCAP];
    __shared__ int s_cnt, s_total, s_pv;

    int b = blockIdx.x, t = threadIdx.x;
    const float* surv = &g_surv[(size_t)b * NN];

    for (int i = t; i < 2048; i += 1024) hist[i] = 0;
    __syncthreads();

    // single histogram sweep
    for (int i = t; i < NN; i += 1024) {
        float v = surv[i];
        if (v > 0.0f) atomicAdd(&hist[(__float_as_uint(v) >> 14) & 2047], 1);
    }
    __syncthreads();

    // pivot: parallel partial sums (8 bins per thread), then short serial scans
    if (t < 256) {
        int s = 0;
        #pragma unroll
        for (int x = 0; x < 8; x++) s += hist[t * 8 + x];
        psum[t] = s;
    }
    __syncthreads();
    if (t == 0) {
        int total = 0;
        for (int g = 0; g < 256; g++) total += psum[g];
        s_total = total;
        int pv = 0;
        if (total >= MAXDET) {
            int cum = 0, g = 255;
            for (; g > 0; g--) {
                if (cum + psum[g] >= MAXDET) break;
                cum += psum[g];
            }
            int x = 7;
            for (; x > 0; x--) {
                int h = hist[g * 8 + x];
                if (cum + h >= MAXDET) break;
                cum += h;
            }
            pv = g * 8 + x;
        }
        s_pv = pv;      // take all bins >= pv  (pv=0 when total<300: take everything)
    }
    __syncthreads();
    int PV = s_pv;

    // gather: everything in bins >= pivot bin
    if (t == 0) s_cnt = 0;
    __syncthreads();
    for (int i = t; i < NN; i += 1024) {
        float v = surv[i];
        if (v > 0.0f) {
            unsigned u = __float_as_uint(v);
            if ((int)((u >> 14) & 2047) >= PV) {
                int s = atomicAdd(&s_cnt, 1);
                if (s < GCAP) gkey[s] = ((u64)(~u) << 32) | (unsigned)i;
            }
        }
    }
    __syncthreads();
    int M = s_cnt; if (M > GCAP) M = GCAP;

    // pad to power of 2 and bitonic sort ascending
    int P = 512; while (P < M) P <<= 1;
    for (int i = M + t; i < P; i += 1024) gkey[i] = ~0ull;
    __syncthreads();
    for (int kk = 2; kk <= P; kk <<= 1) {
        for (int j = kk >> 1; j > 0; j >>= 1) {
            for (int i = t; i < P; i += 1024) {
                int ixj = i ^ j;
                if (ixj > i) {
                    u64 a = gkey[i], bb = gkey[ixj];
                    bool up = ((i & kk) == 0);
                    if ((a > bb) == up) { gkey[i] = bb; gkey[ixj] = a; }
                }
            }
            __syncthreads();
        }
    }

    int kept_n = s_total < MAXDET ? s_total : MAXDET;

    // --- outputs, fully parallel ---
    // dets [BB,300,6]
    for (int e = t; e < MAXDET * 6; e += 1024) {
        int d = e / 6, f = e - d * 6;
        float val = 0.0f;
        if (d < kept_n) {
            u64 key = gkey[d];
            int m = (int)(unsigned)key;
            if (f < 4)      val = g_box[((size_t)b * NN + m) * 4 + f];
            else if (f == 4) val = __uint_as_float(~(unsigned)(key >> 32));
            else             val = g_clsf[(size_t)b * NN + m];
        }
        out[(size_t)b * MAXDET * 6 + e] = val;
    }
    // lg [BB,300,80]
    const size_t LG0 = (size_t)BB * MAXDET * 6;
    for (int e = t; e < MAXDET * 80; e += 1024) {
        int d = e / 80, cc = e - d * 80;
        float val = 0.0f;
        if (d < kept_n) {
            int m = (int)(unsigned)gkey[d];
            val = logits[((size_t)b * NN + m) * 80 + cc];
        }
        out[LG0 + (size_t)b * MAXDET * 80 + e] = val;
    }
    // keep [BB,300]
    const size_t KP0 = (size_t)BB * MAXDET * 86;
    for (int e = t; e < MAXDET; e += 1024) {
        out[KP0 + (size_t)b * MAXDET + e] = (e < kept_n) ? 1.0f : 0.0f;
    }
}

// ---------------- launch ----------------
extern "C" void kernel_launch(void* const* d_in, const int* in_sizes, int n_in,
                              void* d_out, int out_size) {
    const float* pred   = (const float*)d_in[0];
    const float* logits = (const float*)d_in[1];
    float* out = (float*)d_out;

    k_prep<<<BB * NN / PB, PB>>>(pred);     // 3150 blocks, one thread per box
    k_nms<<<BB * NCC, 256>>>();             // also resets g_cnt for the next run
    k_select<<<BB, 1024>>>(logits, out);
}